// round 4
// baseline (speedup 1.0000x reference)
#include <cuda_runtime.h>
#include <cuda_bf16.h>
#include <math.h>

#define BB 4
#define TT 2048
#define CC 1024
#define HH 2048

// Scratch (device globals: allocation-free rule)
__device__ float g_q[(size_t)BB * TT * HH];
__device__ float g_k[(size_t)BB * TT * HH];
__device__ float g_v[(size_t)BB * TT * HH];
__device__ float g_s[(size_t)BB * TT * TT];

// ---------------------------------------------------------------------------
// C = scale * A * B^T   (A: [M,K] row-major, B: [N,K] row-major, C: [M,N])
// 128x128 block, BK=8, 256 threads, 8x8 microtile.
// causal: skip blocks with bx > by (BM==BN==128, square M==N assumed)
// ---------------------------------------------------------------------------
__global__ __launch_bounds__(256, 2)
void sgemm_nt(const float* __restrict__ A, const float* __restrict__ B,
              float* __restrict__ C, int M, int N, int K, float scale,
              int causal, long long sA, long long sB, long long sC)
{
    int bz = blockIdx.z;
    A += (long long)bz * sA;
    B += (long long)bz * sB;
    C += (long long)bz * sC;

    int bx = blockIdx.x;   // N-block
    int by = blockIdx.y;   // M-block
    if (causal && bx > by) return;

    __shared__ float As[8][128];
    __shared__ float Bs[8][128];

    int tid = threadIdx.x;
    int tx = tid & 15;     // 0..15 -> col group
    int ty = tid >> 4;     // 0..15 -> row group

    int lrow = tid >> 1;          // 0..127
    int lcol = (tid & 1) * 4;     // 0 or 4

    const float* Aptr = A + (long long)(by * 128 + lrow) * K + lcol;
    const float* Bptr = B + (long long)(bx * 128 + lrow) * K + lcol;

    float acc[8][8];
#pragma unroll
    for (int i = 0; i < 8; i++)
#pragma unroll
        for (int j = 0; j < 8; j++) acc[i][j] = 0.f;

    for (int kt = 0; kt < K; kt += 8) {
        float4 av = *(const float4*)(Aptr + kt);
        float4 bv = *(const float4*)(Bptr + kt);
        __syncthreads();
        As[lcol + 0][lrow] = av.x; As[lcol + 1][lrow] = av.y;
        As[lcol + 2][lrow] = av.z; As[lcol + 3][lrow] = av.w;
        Bs[lcol + 0][lrow] = bv.x; Bs[lcol + 1][lrow] = bv.y;
        Bs[lcol + 2][lrow] = bv.z; Bs[lcol + 3][lrow] = bv.w;
        __syncthreads();

#pragma unroll
        for (int k = 0; k < 8; k++) {
            float a[8], b[8];
            *(float4*)(a)     = *(const float4*)&As[k][ty * 8];
            *(float4*)(a + 4) = *(const float4*)&As[k][ty * 8 + 4];
            *(float4*)(b)     = *(const float4*)&Bs[k][tx * 8];
            *(float4*)(b + 4) = *(const float4*)&Bs[k][tx * 8 + 4];
#pragma unroll
            for (int i = 0; i < 8; i++)
#pragma unroll
                for (int j = 0; j < 8; j++)
                    acc[i][j] = fmaf(a[i], b[j], acc[i][j]);
        }
    }

#pragma unroll
    for (int i = 0; i < 8; i++) {
        int r = by * 128 + ty * 8 + i;
        float* cp = C + (long long)r * N + bx * 128 + tx * 8;
        float4 o0, o1;
        o0.x = acc[i][0] * scale; o0.y = acc[i][1] * scale;
        o0.z = acc[i][2] * scale; o0.w = acc[i][3] * scale;
        o1.x = acc[i][4] * scale; o1.y = acc[i][5] * scale;
        o1.z = acc[i][6] * scale; o1.w = acc[i][7] * scale;
        *(float4*)(cp)     = o0;
        *(float4*)(cp + 4) = o1;
    }
}

// ---------------------------------------------------------------------------
// C = A * B   (A: [M,K] row-major, B: [K,N] row-major, C: [M,N])
// causal_klimit: k-loop bounded at (by+1)*128 (valid P columns only)
// ---------------------------------------------------------------------------
__global__ __launch_bounds__(256, 2)
void sgemm_nn(const float* __restrict__ A, const float* __restrict__ B,
              float* __restrict__ C, int M, int N, int K,
              int causal_klimit, long long sA, long long sB, long long sC)
{
    int bz = blockIdx.z;
    A += (long long)bz * sA;
    B += (long long)bz * sB;
    C += (long long)bz * sC;

    int bx = blockIdx.x;   // N-block
    int by = blockIdx.y;   // M-block

    __shared__ float As[8][128];
    __shared__ float Bs[8][128];

    int tid = threadIdx.x;
    int tx = tid & 15;
    int ty = tid >> 4;

    int larow = tid >> 1;
    int lacol = (tid & 1) * 4;
    int lbrow = tid >> 5;          // 0..7 (k within tile)
    int lbcol = (tid & 31) * 4;    // 0..124

    const float* Aptr = A + (long long)(by * 128 + larow) * K + lacol;
    const float* Bptr = B + (long long)lbrow * N + bx * 128 + lbcol;

    int kend = causal_klimit ? min(K, (by + 1) * 128) : K;

    float acc[8][8];
#pragma unroll
    for (int i = 0; i < 8; i++)
#pragma unroll
        for (int j = 0; j < 8; j++) acc[i][j] = 0.f;

    for (int kt = 0; kt < kend; kt += 8) {
        float4 av = *(const float4*)(Aptr + kt);
        float4 bv = *(const float4*)(Bptr + (long long)kt * N);
        __syncthreads();
        As[lacol + 0][larow] = av.x; As[lacol + 1][larow] = av.y;
        As[lacol + 2][larow] = av.z; As[lacol + 3][larow] = av.w;
        *(float4*)&Bs[lbrow][lbcol] = bv;
        __syncthreads();

#pragma unroll
        for (int k = 0; k < 8; k++) {
            float a[8], b[8];
            *(float4*)(a)     = *(const float4*)&As[k][ty * 8];
            *(float4*)(a + 4) = *(const float4*)&As[k][ty * 8 + 4];
            *(float4*)(b)     = *(const float4*)&Bs[k][tx * 8];
            *(float4*)(b + 4) = *(const float4*)&Bs[k][tx * 8 + 4];
#pragma unroll
            for (int i = 0; i < 8; i++)
#pragma unroll
                for (int j = 0; j < 8; j++)
                    acc[i][j] = fmaf(a[i], b[j], acc[i][j]);
        }
    }

#pragma unroll
    for (int i = 0; i < 8; i++) {
        int r = by * 128 + ty * 8 + i;
        float* cp = C + (long long)r * N + bx * 128 + tx * 8;
        *(float4*)(cp)     = *(float4*)&acc[i][0];
        *(float4*)(cp + 4) = *(float4*)&acc[i][4];
    }
}

// ---------------------------------------------------------------------------
// Causal row softmax in-place on S[B,T,T]. One block per row.
// Also zero-fills s in (t, diag-block end) so PV GEMM needs no masking.
// ---------------------------------------------------------------------------
__device__ __forceinline__ float warp_max(float v) {
#pragma unroll
    for (int o = 16; o; o >>= 1) v = fmaxf(v, __shfl_xor_sync(0xffffffffu, v, o));
    return v;
}
__device__ __forceinline__ float warp_sum(float v) {
#pragma unroll
    for (int o = 16; o; o >>= 1) v += __shfl_xor_sync(0xffffffffu, v, o);
    return v;
}

__global__ __launch_bounds__(256)
void softmax_causal(float* __restrict__ S, int T)
{
    int row = blockIdx.x;        // 0 .. B*T-1
    int b = row / T;
    int t = row - b * T;
    float* p = S + (long long)b * T * T + (long long)t * T;
    int n = t + 1;

    int tid = threadIdx.x;
    int lane = tid & 31, wid = tid >> 5;
    __shared__ float red[8];

    // max
    float m = -INFINITY;
    for (int i = tid; i < n; i += 256) m = fmaxf(m, p[i]);
    m = warp_max(m);
    if (lane == 0) red[wid] = m;
    __syncthreads();
    if (wid == 0) {
        float x = (lane < 8) ? red[lane] : -INFINITY;
        x = warp_max(x);
        if (lane == 0) red[0] = x;
    }
    __syncthreads();
    m = red[0];
    __syncthreads();

    // exp + sum (store exp in place)
    float s = 0.f;
    for (int i = tid; i < n; i += 256) {
        float e = __expf(p[i] - m);
        p[i] = e;
        s += e;
    }
    s = warp_sum(s);
    if (lane == 0) red[wid] = s;
    __syncthreads();
    if (wid == 0) {
        float x = (lane < 8) ? red[lane] : 0.f;
        x = warp_sum(x);
        if (lane == 0) red[0] = x;
    }
    __syncthreads();
    float inv = 1.f / red[0];

    for (int i = tid; i < n; i += 256) p[i] *= inv;

    // zero tail to end of this row's 128-wide diagonal block
    int zend = min(T, ((t >> 7) + 1) << 7);
    for (int i = n + tid; i < zend; i += 256) p[i] = 0.f;
}

// ---------------------------------------------------------------------------
extern "C" void kernel_launch(void* const* d_in, const int* in_sizes, int n_in,
                              void* d_out, int out_size)
{
    const float* x  = (const float*)d_in[0];   // [B,T,C]
    const float* Wk = (const float*)d_in[1];   // [H,C]
    const float* Wq = (const float*)d_in[2];   // [H,C]
    const float* Wv = (const float*)d_in[3];   // [H,C]
    float* out = (float*)d_out;                // [B,T,H]

    float* q; cudaGetSymbolAddress((void**)&q, g_q);
    float* k; cudaGetSymbolAddress((void**)&k, g_k);
    float* v; cudaGetSymbolAddress((void**)&v, g_v);
    float* s; cudaGetSymbolAddress((void**)&s, g_s);

    const int M = BB * TT;           // 8192
    const float scale = rsqrtf((float)HH);

    // 1) Projections: [M,C] x [H,C]^T -> [M,H]
    dim3 gp(HH / 128, M / 128, 1);
    sgemm_nt<<<gp, 256>>>(x, Wq, q, M, HH, CC, 1.f, 0, 0, 0, 0);
    sgemm_nt<<<gp, 256>>>(x, Wk, k, M, HH, CC, 1.f, 0, 0, 0, 0);
    sgemm_nt<<<gp, 256>>>(x, Wv, v, M, HH, CC, 1.f, 0, 0, 0, 0);

    // 2) Scores: S_b = scale * Q_b K_b^T   (causal block skip)
    dim3 gs(TT / 128, TT / 128, BB);
    sgemm_nt<<<gs, 256>>>(q, k, s, TT, TT, HH, scale, 1,
                          (long long)TT * HH, (long long)TT * HH,
                          (long long)TT * TT);

    // 3) Causal softmax rows (in-place) + zero diag-block tail
    softmax_causal<<<BB * TT, 256>>>(s, TT);

    // 4) O_b = P_b V_b  (k-loop limited per block row)
    dim3 go(HH / 128, TT / 128, BB);
    sgemm_nn<<<go, 256>>>(s, v, out, TT, HH, TT, 1,
                          (long long)TT * TT, (long long)TT * HH,
                          (long long)TT * HH);
}